// round 8
// baseline (speedup 1.0000x reference)
#include <cuda_runtime.h>

// out[i] = cos(x[i]) * cos(theta[i & 63])
// N = 33,554,432 fp32 -> 8,388,608 float4.
//
// CONVERGED-ROOFLINE kernel. Six structurally different variants all measure
// 5.6-5.9 TB/s (~73% of 8 TB/s spec) with the SM nearly idle (issue<17%,
// fma<7%): this is the HBM3e mixed 1:1 read:write ceiling for streaming
// traffic. 268 MB of traffic is compulsory. Config: 512-thread CTAs, 64B per
// thread, front-batched MLP=4 loads, all compute batched, then back-to-back
// STG.128 (grouped store wavefronts).
// Per-thread inner stride = 512 float4 = 2048 floats == 0 mod 64, so each
// thread's theta vector is invariant across its 4 iterations.

#define THREADS 512
#define UNROLL  4
#define CHUNK   (THREADS * UNROLL)     // 2048 float4 per block

__global__ void __launch_bounds__(THREADS) qab_kernel(
    const float4* __restrict__ x4,
    const float* __restrict__ theta,
    float4* __restrict__ out4,
    int nvec)
{
    __shared__ float ct[64];
    if (threadIdx.x < 64) {
        ct[threadIdx.x] = cosf(theta[threadIdx.x]);   // accurate; 64 values
    }
    __syncthreads();

    const int base = blockIdx.x * CHUNK + threadIdx.x;
    const int t = (base << 2) & 63;                    // 16B-aligned theta slot
    const float4 c = *reinterpret_cast<const float4*>(&ct[t]);

    if (base + (UNROLL - 1) * THREADS < nvec) {
        // Phase 1: front-batch all 4 LDG.128 (MLP=4)
        float4 v[UNROLL];
        #pragma unroll
        for (int k = 0; k < UNROLL; k++)
            v[k] = x4[base + k * THREADS];

        // Phase 2: all 16 MUFU + FMUL
        float4 r[UNROLL];
        #pragma unroll
        for (int k = 0; k < UNROLL; k++) {
            r[k].x = __cosf(v[k].x) * c.x;
            r[k].y = __cosf(v[k].y) * c.y;
            r[k].z = __cosf(v[k].z) * c.z;
            r[k].w = __cosf(v[k].w) * c.w;
        }

        // Phase 3: back-to-back STG.128
        #pragma unroll
        for (int k = 0; k < UNROLL; k++)
            out4[base + k * THREADS] = r[k];
    } else {
        // Tail path (unused for the shipped shape; kept for generality)
        #pragma unroll
        for (int k = 0; k < UNROLL; k++) {
            int i = base + k * THREADS;
            if (i < nvec) {
                float4 v = x4[i];
                float4 r;
                r.x = __cosf(v.x) * c.x;
                r.y = __cosf(v.y) * c.y;
                r.z = __cosf(v.z) * c.z;
                r.w = __cosf(v.w) * c.w;
                out4[i] = r;
            }
        }
    }
}

extern "C" void kernel_launch(void* const* d_in, const int* in_sizes, int n_in,
                              void* d_out, int out_size)
{
    const float* x     = (const float*)d_in[0];
    const float* theta = (const float*)d_in[1];
    float* out         = (float*)d_out;

    int n    = out_size;          // total elements (33,554,432)
    int nvec = n >> 2;            // float4 count (8,388,608)

    int blocks = (nvec + CHUNK - 1) / CHUNK;   // 4096 for the shipped shape

    qab_kernel<<<blocks, THREADS>>>(
        (const float4*)x, theta, (float4*)out, nvec);
}